// round 11
// baseline (speedup 1.0000x reference)
#include <cuda_runtime.h>
#include <cuda_bf16.h>
#include <math.h>

#define NR 8192
#define DIM 256
#define NC 16

// ---------------- scratch (device globals; no allocation) ----------------
__device__ float g_buf1[NR * DIM];     // mx -> H1
__device__ float g_buf2[NR * DIM];     // nom
__device__ float g_gm1[NR];
__device__ float g_denom[NR];
__device__ float g_srow[NR];
__device__ float g_h2[NR];
__device__ float g_p[DIM * 64];        // [W_logits | p_ks^T | 0-pad] (256 x 64)
__device__ float g_s[NR * 64];         // H1 @ P
__device__ float g_kc[NC * 4];         // a_n, pa, p2, lam
__device__ float g_logits[NR * NC];
__device__ float g_part[16 * NR * NC]; // split-K partials of final GEMM
// split-bf16 operands for the big tensor-core GEMM
__device__ unsigned short g_ahi[NR * NR];        // 128 MB
__device__ unsigned short g_alo[NR * NR];        // 128 MB
__device__ unsigned short g_bthi[DIM * NR];      // Bg^T hi (256 x 8192)
__device__ unsigned short g_btlo[DIM * NR];      // Bg^T lo

// ---------------- helpers ----------------
__device__ __forceinline__ unsigned long long pack2(float lo, float hi) {
    unsigned long long r;
    asm("mov.b64 %0, {%1, %2};" : "=l"(r) : "r"(__float_as_uint(lo)), "r"(__float_as_uint(hi)));
    return r;
}
__device__ __forceinline__ float2 unpack2(unsigned long long v) {
    unsigned int lo, hi;
    asm("mov.b64 {%0, %1}, %2;" : "=r"(lo), "=r"(hi) : "l"(v));
    float2 f; f.x = __uint_as_float(lo); f.y = __uint_as_float(hi); return f;
}
__device__ __forceinline__ unsigned long long ffma2(unsigned long long a, unsigned long long b,
                                                    unsigned long long c) {
    unsigned long long d;
    asm("fma.rn.f32x2 %0, %1, %2, %3;" : "=l"(d) : "l"(a), "l"(b), "l"(c));
    return d;
}
__device__ __forceinline__ float wsum(float v) {
#pragma unroll
    for (int o = 16; o; o >>= 1) v += __shfl_xor_sync(0xffffffffu, v, o);
    return v;
}
__device__ __forceinline__ float atanh_clip(float x) {
    return atanhf(fminf(x, 1.0f - 1e-7f));
}
__device__ __forceinline__ unsigned int smem_u32(const void* p) {
    unsigned int a;
    asm("{ .reg .u64 t; cvta.to.shared.u64 t, %1; cvt.u32.u64 %0, t; }" : "=r"(a) : "l"(p));
    return a;
}
__device__ __forceinline__ void ldsm4(unsigned* r, unsigned addr) {
    asm volatile("ldmatrix.sync.aligned.m8n8.x4.shared.b16 {%0,%1,%2,%3}, [%4];"
                 : "=r"(r[0]), "=r"(r[1]), "=r"(r[2]), "=r"(r[3]) : "r"(addr));
}
__device__ __forceinline__ void mma16816(float* d, const unsigned* a,
                                         unsigned b0, unsigned b1) {
    asm volatile(
        "mma.sync.aligned.m16n8k16.row.col.f32.bf16.bf16.f32 "
        "{%0,%1,%2,%3}, {%4,%5,%6,%7}, {%8,%9}, {%0,%1,%2,%3};"
        : "+f"(d[0]), "+f"(d[1]), "+f"(d[2]), "+f"(d[3])
        : "r"(a[0]), "r"(a[1]), "r"(a[2]), "r"(a[3]), "r"(b0), "r"(b1));
}

// ---------------- mx = X @ W^T (both K-contiguous; NT GEMM, no transpose pass) ----------------
// BM=128, BN=64, BK=16, 256 threads, grid (64, 4). C row stride = DIM.
__global__ void __launch_bounds__(256) gemm_xwt(const float* __restrict__ X,
                                                const float* __restrict__ W,
                                                float* __restrict__ C) {
    __shared__ float As[16][132];
    __shared__ float Bs[16][64];
    int t = threadIdx.x;
    int bm = blockIdx.x * 128;
    int bn = blockIdx.y * 64;
    int m0 = (t >> 4) * 8;
    int n0 = (t & 15) * 4;
    int arow = t >> 2;
    int aq = (t & 3) * 4;
    unsigned long long acc[8][2];
#pragma unroll
    for (int i = 0; i < 8; i++) { acc[i][0] = 0ull; acc[i][1] = 0ull; }

    for (int k0 = 0; k0 < DIM; k0 += 16) {
#pragma unroll
        for (int i = 0; i < 2; i++) {
            int r = arow + i * 64;
            float4 v = *(const float4*)(X + (size_t)(bm + r) * DIM + k0 + aq);
            As[aq + 0][r] = v.x; As[aq + 1][r] = v.y;
            As[aq + 2][r] = v.z; As[aq + 3][r] = v.w;
        }
        {
            int r = t >> 2;    // 0..63 W row within tile
            float4 v = *(const float4*)(W + (size_t)(bn + r) * DIM + k0 + aq);
            Bs[aq + 0][r] = v.x; Bs[aq + 1][r] = v.y;
            Bs[aq + 2][r] = v.z; Bs[aq + 3][r] = v.w;
        }
        __syncthreads();
#pragma unroll
        for (int kk = 0; kk < 16; kk++) {
            float4 a0 = *(const float4*)&As[kk][m0];
            float4 a1 = *(const float4*)&As[kk][m0 + 4];
            float4 b  = *(const float4*)&Bs[kk][n0];
            unsigned long long b01 = pack2(b.x, b.y);
            unsigned long long b23 = pack2(b.z, b.w);
            float am[8] = {a0.x, a0.y, a0.z, a0.w, a1.x, a1.y, a1.z, a1.w};
#pragma unroll
            for (int i = 0; i < 8; i++) {
                unsigned long long ad = pack2(am[i], am[i]);
                acc[i][0] = ffma2(ad, b01, acc[i][0]);
                acc[i][1] = ffma2(ad, b23, acc[i][1]);
            }
        }
        __syncthreads();
    }
#pragma unroll
    for (int i = 0; i < 8; i++) {
        float2 lo = unpack2(acc[i][0]);
        float2 hi = unpack2(acc[i][1]);
        *(float4*)(C + (size_t)(bm + m0 + i) * DIM + bn + n0) =
            make_float4(lo.x, lo.y, hi.x, hi.y);
    }
}

// ---------------- generic NN GEMM (kept for S = H1 @ P) ----------------
__global__ void __launch_bounds__(256) gemm_nn_kernel(const float* __restrict__ A,
                                                      const float* __restrict__ B,
                                                      float* __restrict__ C,
                                                      int K, int N) {
    __shared__ float As[16][132];
    __shared__ float Bs[16][64];
    int t = threadIdx.x;
    int bm = blockIdx.x * 128;
    int bn = blockIdx.y * 64;
    int m0 = (t >> 4) * 8;
    int n0 = (t & 15) * 4;
    int arow = t >> 2;
    int aq = (t & 3) * 4;
    int brow = t >> 4;
    int bq = (t & 15) * 4;
    unsigned long long acc[8][2];
#pragma unroll
    for (int i = 0; i < 8; i++) { acc[i][0] = 0ull; acc[i][1] = 0ull; }
    const float* Ab = A + (size_t)bm * K;
    const float* Bb = B + bn;
    for (int k0 = 0; k0 < K; k0 += 16) {
#pragma unroll
        for (int i = 0; i < 2; i++) {
            int r = arow + i * 64;
            float4 v = *(const float4*)(Ab + (size_t)r * K + k0 + aq);
            As[aq + 0][r] = v.x; As[aq + 1][r] = v.y;
            As[aq + 2][r] = v.z; As[aq + 3][r] = v.w;
        }
        {
            float4 v = *(const float4*)(Bb + (size_t)(k0 + brow) * N + bq);
            *(float4*)&Bs[brow][bq] = v;
        }
        __syncthreads();
#pragma unroll
        for (int kk = 0; kk < 16; kk++) {
            float4 a0 = *(const float4*)&As[kk][m0];
            float4 a1 = *(const float4*)&As[kk][m0 + 4];
            float4 b  = *(const float4*)&Bs[kk][n0];
            unsigned long long b01 = pack2(b.x, b.y);
            unsigned long long b23 = pack2(b.z, b.w);
            float am[8] = {a0.x, a0.y, a0.z, a0.w, a1.x, a1.y, a1.z, a1.w};
#pragma unroll
            for (int i = 0; i < 8; i++) {
                unsigned long long ad = pack2(am[i], am[i]);
                acc[i][0] = ffma2(ad, b01, acc[i][0]);
                acc[i][1] = ffma2(ad, b23, acc[i][1]);
            }
        }
        __syncthreads();
    }
#pragma unroll
    for (int i = 0; i < 8; i++) {
        float2 lo = unpack2(acc[i][0]);
        float2 hi = unpack2(acc[i][1]);
        float4 v = make_float4(lo.x, lo.y, hi.x, hi.y);
        *(float4*)(C + (size_t)(bm + m0 + i) * N + bn + n0) = v;
    }
}

// ---------------- fused: mobius_matvec scale + gamma + transposed bf16 split ----------------
// Each block: 32 rows. Phase 1: per-row norms/scales into smem. Phase 2: coalesced
// transposed writes of Bg^T hi/lo. Also writes gm1. Replaces rowwise1 + transposeB_split.
__global__ void __launch_bounds__(256) rowwise_trans(const float* __restrict__ X,
                                                     const float* __restrict__ MX,
                                                     unsigned short* __restrict__ Thi,
                                                     unsigned short* __restrict__ Tlo,
                                                     float* __restrict__ gm1) {
    __shared__ float sm[32][257];
    int jb = blockIdx.x * 32;
    int wd = threadIdx.x >> 5, lane = threadIdx.x & 31;
#pragma unroll
    for (int rr = 0; rr < 4; rr++) {
        int lr = wd * 4 + rr;
        int j = jb + lr;
        const float4* xr = (const float4*)(X + (size_t)j * DIM) + lane * 2;
        const float4* mr = (const float4*)(MX + (size_t)j * DIM) + lane * 2;
        float4 x0 = xr[0], x1 = xr[1];
        float4 m0 = mr[0], m1 = mr[1];
        float xs = x0.x * x0.x + x0.y * x0.y + x0.z * x0.z + x0.w * x0.w +
                   x1.x * x1.x + x1.y * x1.y + x1.z * x1.z + x1.w * x1.w;
        float ms = m0.x * m0.x + m0.y * m0.y + m0.z * m0.z + m0.w * m0.w +
                   m1.x * m1.x + m1.y * m1.y + m1.z * m1.z + m1.w * m1.w;
        xs = wsum(xs); ms = wsum(ms);
        float xn  = fmaxf(sqrtf(xs), 1e-15f);
        float mxn = fmaxf(sqrtf(ms), 1e-15f);
        float s = tanhf(mxn / xn * atanh_clip(xn)) / mxn;
        float g = 2.0f / fmaxf(1.0f - s * s * ms, 1e-10f);
        float gs = g * s;
        int d0 = lane * 8;
        sm[lr][d0 + 0] = m0.x * gs; sm[lr][d0 + 1] = m0.y * gs;
        sm[lr][d0 + 2] = m0.z * gs; sm[lr][d0 + 3] = m0.w * gs;
        sm[lr][d0 + 4] = m1.x * gs; sm[lr][d0 + 5] = m1.y * gs;
        sm[lr][d0 + 6] = m1.z * gs; sm[lr][d0 + 7] = m1.w * gs;
        if (lane == 0) gm1[j] = g - 1.0f;
    }
    __syncthreads();
    int gidx = threadIdx.x >> 3;       // 0..31: d within pass
    int l3 = threadIdx.x & 7;          // 8 threads cover 32 j's
#pragma unroll
    for (int pass = 0; pass < 8; pass++) {
        int d = pass * 32 + gidx;
        unsigned short h4[4], l4[4];
#pragma unroll
        for (int jj = 0; jj < 4; jj++) {
            float v = sm[l3 * 4 + jj][d];
            __nv_bfloat16 h = __float2bfloat16_rn(v);
            float rem = v - __bfloat162float(h);
            __nv_bfloat16 l = __float2bfloat16_rn(rem);
            h4[jj] = __bfloat16_as_ushort(h);
            l4[jj] = __bfloat16_as_ushort(l);
        }
        uint2 hv, lv;
        hv.x = (unsigned)h4[0] | ((unsigned)h4[1] << 16);
        hv.y = (unsigned)h4[2] | ((unsigned)h4[3] << 16);
        lv.x = (unsigned)l4[0] | ((unsigned)l4[1] << 16);
        lv.y = (unsigned)l4[2] | ((unsigned)l4[3] << 16);
        *(uint2*)(Thi + (size_t)d * NR + jb + l3 * 4) = hv;
        *(uint2*)(Tlo + (size_t)d * NR + jb + l3 * 4) = lv;
    }
}

// ---------------- convert A -> A_hi/A_lo bf16, fused row dots ----------------
__global__ void __launch_bounds__(256) convertA_dot(const float* __restrict__ A,
                                                    const float* __restrict__ gm1,
                                                    unsigned short* __restrict__ Ahi,
                                                    unsigned short* __restrict__ Alo,
                                                    float* __restrict__ denom,
                                                    float* __restrict__ srow) {
    int row = blockIdx.x;
    const float4* ar = (const float4*)(A + (size_t)row * NR);
    const float4* gr = (const float4*)gm1;
    uint2* hi4 = (uint2*)(Ahi + (size_t)row * NR);
    uint2* lo4 = (uint2*)(Alo + (size_t)row * NR);
    float d = 0.f, ss = 0.f;
    for (int j = threadIdx.x; j < NR / 4; j += 256) {
        float4 a = ar[j];
        float4 g = gr[j];
        d += a.x * g.x + a.y * g.y + a.z * g.z + a.w * g.w;
        ss += a.x + a.y + a.z + a.w;
        float av[4] = {a.x, a.y, a.z, a.w};
        unsigned int hb[4], lb[4];
#pragma unroll
        for (int q = 0; q < 4; q++) {
            __nv_bfloat16 h = __float2bfloat16_rn(av[q]);
            float rem = av[q] - __bfloat162float(h);
            __nv_bfloat16 l = __float2bfloat16_rn(rem);
            hb[q] = __bfloat16_as_ushort(h);
            lb[q] = __bfloat16_as_ushort(l);
        }
        uint2 hv, lv;
        hv.x = hb[0] | (hb[1] << 16); hv.y = hb[2] | (hb[3] << 16);
        lv.x = lb[0] | (lb[1] << 16); lv.y = lb[2] | (lb[3] << 16);
        hi4[j] = hv; lo4[j] = lv;
    }
    __shared__ float sd[8], sss[8];
    d = wsum(d); ss = wsum(ss);
    int lane = threadIdx.x & 31, wp = threadIdx.x >> 5;
    if (lane == 0) { sd[wp] = d; sss[wp] = ss; }
    __syncthreads();
    if (wp == 0) {
        d = (lane < 8) ? sd[lane] : 0.f;
        ss = (lane < 8) ? sss[lane] : 0.f;
        d = wsum(d); ss = wsum(ss);
        if (lane == 0) {
            if (fabsf(d) < 1e-10f) d = 1e-10f;
            denom[row] = d;
            srow[row] = ss;
        }
    }
}

// ---------------- big GEMM via mma.sync (split bf16, fp32 accum) ----------------
#define STG_BYTES 65536
#define SMEM_TOTAL_MMA (3 * STG_BYTES)

__device__ __forceinline__ void load_stage(unsigned int sb, int s, int k0, int bm, int bn,
                                           const unsigned short* Ahi, const unsigned short* Alo,
                                           const unsigned short* Bhi, const unsigned short* Blo,
                                           int tid) {
    unsigned int stg = sb + s * STG_BYTES;
#pragma unroll
    for (int t = 0; t < 16; t++) {
        int idx = tid + 256 * t;              // 0..4095
        int tile = idx >> 10;                 // 0..3
        int c = idx & 1023;
        int r = c >> 3;                       // 0..127
        int ch = c & 7;                       // 16B chunk in 128B row
        const unsigned short* g;
        int grow;
        if (tile == 0)      { g = Ahi; grow = bm + r; }
        else if (tile == 1) { g = Alo; grow = bm + r; }
        else if (tile == 2) { g = Bhi; grow = bn + r; }
        else                { g = Blo; grow = bn + r; }
        const unsigned short* src = g + (size_t)grow * NR + k0 + ch * 8;
        unsigned int off = (unsigned)(r << 7) + (unsigned)(ch << 4);
        unsigned int dst = stg + (tile << 14) + (off ^ ((off >> 3) & 0x70));
        asm volatile("cp.async.cg.shared.global [%0], [%1], 16;" :: "r"(dst), "l"(src));
    }
}

__global__ void __launch_bounds__(256, 1) hmma_gemm_kernel(const unsigned short* __restrict__ Ahi,
                                                           const unsigned short* __restrict__ Alo,
                                                           const unsigned short* __restrict__ Bhi,
                                                           const unsigned short* __restrict__ Blo,
                                                           float* __restrict__ C) {
    extern __shared__ char smem[];
    unsigned int sb = smem_u32(smem);
    int tid = threadIdx.x;
    int wid = tid >> 5;
    int lane = tid & 31;
    int bm = (blockIdx.x >> 1) * 128;
    int bn = (blockIdx.x & 1) * 128;
    int wm = (wid & 3) * 32;      // warp M offset in tile
    int wn = (wid >> 2) * 64;     // warp N offset in tile

    int lrow = (lane & 7) + ((lane >> 3) & 1) * 8;   // row within 16
    int lcol = (lane >> 4) * 16;                     // 0 or 16 bytes (k half)

    float acc[2][8][4];
#pragma unroll
    for (int a = 0; a < 2; a++)
#pragma unroll
        for (int b = 0; b < 8; b++)
#pragma unroll
            for (int c = 0; c < 4; c++) acc[a][b][c] = 0.f;

#pragma unroll
    for (int s = 0; s < 3; s++) {
        load_stage(sb, s, s * 64, bm, bn, Ahi, Alo, Bhi, Blo, tid);
        asm volatile("cp.async.commit_group;" ::: "memory");
    }

    for (int k = 0; k < 128; k++) {
        int s = k - (k / 3) * 3;
        asm volatile("cp.async.wait_group 2;" ::: "memory");
        __syncthreads();
        unsigned int stg = sb + s * STG_BYTES;
#pragma unroll
        for (int ks = 0; ks < 4; ks++) {
            int bcol = ks * 32 + lcol;
            unsigned Ah[2][4], Al[2][4];
#pragma unroll
            for (int mf = 0; mf < 2; mf++) {
                int row = wm + mf * 16 + lrow;
                unsigned base = (unsigned)(row << 7) + ((unsigned)bcol ^ ((row & 7) << 4));
                ldsm4(Ah[mf], stg + base);
                ldsm4(Al[mf], stg + 16384 + base);
            }
            unsigned Bh[4][4], Bl[4][4];
#pragma unroll
            for (int g = 0; g < 4; g++) {
                int row = wn + g * 16 + lrow;
                unsigned base = (unsigned)(row << 7) + ((unsigned)bcol ^ ((row & 7) << 4));
                ldsm4(Bh[g], stg + 32768 + base);
                ldsm4(Bl[g], stg + 49152 + base);
            }
#pragma unroll
            for (int mf = 0; mf < 2; mf++)
#pragma unroll
                for (int g = 0; g < 4; g++)
#pragma unroll
                    for (int j = 0; j < 2; j++) {
                        float* d = acc[mf][g * 2 + j];
                        mma16816(d, Ah[mf], Bh[g][j], Bh[g][j + 2]);
                        mma16816(d, Ah[mf], Bl[g][j], Bl[g][j + 2]);
                        mma16816(d, Al[mf], Bh[g][j], Bh[g][j + 2]);
                    }
        }
        __syncthreads();
        if (k + 3 < 128)
            load_stage(sb, s, (k + 3) * 64, bm, bn, Ahi, Alo, Bhi, Blo, tid);
        asm volatile("cp.async.commit_group;" ::: "memory");
    }

#pragma unroll
    for (int mf = 0; mf < 2; mf++) {
        int row0 = bm + wm + mf * 16 + (lane >> 2);
#pragma unroll
        for (int f = 0; f < 8; f++) {
            int col = bn + wn + f * 8 + (lane & 3) * 2;
            *(float2*)&C[(size_t)row0 * DIM + col] = make_float2(acc[mf][f][0], acc[mf][f][1]);
            *(float2*)&C[(size_t)(row0 + 8) * DIM + col] = make_float2(acc[mf][f][2], acc[mf][f][3]);
        }
    }
}

// ---------------- row-wise 2: two_mean -> H1, h2 ----------------
__global__ void __launch_bounds__(256) rowwise_h1_kernel(const float* __restrict__ NOM,
                                                         const float* __restrict__ denom,
                                                         const float* __restrict__ srow,
                                                         float* __restrict__ H1,
                                                         float* __restrict__ h2out) {
    int w = (blockIdx.x << 3) + (threadIdx.x >> 5);
    int lane = threadIdx.x & 31;
    const float4* nr = (const float4*)(NOM + (size_t)w * DIM) + lane * 2;
    float4 v0 = nr[0], v1 = nr[1];
    float dinv = 1.0f / denom[w];
    float t[8] = {v0.x * dinv, v0.y * dinv, v0.z * dinv, v0.w * dinv,
                  v1.x * dinv, v1.y * dinv, v1.z * dinv, v1.w * dinv};
    float s2 = 0.f;
#pragma unroll
    for (int i = 0; i < 8; i++) s2 += t[i] * t[i];
    s2 = wsum(s2);
    float tn = fmaxf(sqrtf(s2), 1e-15f);
    float c1 = tanhf(0.5f * atanh_clip(tn)) / tn;
#pragma unroll
    for (int i = 0; i < 8; i++) t[i] *= c1;
    s2 = 0.f;
#pragma unroll
    for (int i = 0; i < 8; i++) s2 += t[i] * t[i];
    s2 = wsum(s2);
    float mn = fmaxf(sqrtf(s2), 1e-15f);
    float c2 = tanhf(srow[w] * atanh_clip(mn)) / mn;
#pragma unroll
    for (int i = 0; i < 8; i++) t[i] *= c2;
    s2 = 0.f;
#pragma unroll
    for (int i = 0; i < 8; i++) s2 += t[i] * t[i];
    s2 = wsum(s2);
    float yn = fmaxf(sqrtf(s2), 1e-15f);
    float c3 = atanh_clip(yn) / yn;
#pragma unroll
    for (int i = 0; i < 8; i++) t[i] = fmaxf(t[i] * c3, 0.0f);
    s2 = 0.f;
#pragma unroll
    for (int i = 0; i < 8; i++) s2 += t[i] * t[i];
    s2 = wsum(s2);
    float rn = fmaxf(sqrtf(s2), 1e-15f);
    float c4 = tanhf(rn) / rn;
#pragma unroll
    for (int i = 0; i < 8; i++) t[i] *= c4;
    s2 = 0.f;
#pragma unroll
    for (int i = 0; i < 8; i++) s2 += t[i] * t[i];
    s2 = wsum(s2);
    float4* hr = (float4*)(H1 + (size_t)w * DIM) + lane * 2;
    hr[0] = make_float4(t[0], t[1], t[2], t[3]);
    hr[1] = make_float4(t[4], t[5], t[6], t[7]);
    if (lane == 0) h2out[w] = s2;
}

// ---------------- build P = [W_logits | p_ks^T | 0] (256 x 64) ----------------
__global__ void buildP_kernel(const float* __restrict__ Wl, const float* __restrict__ pks,
                              float* __restrict__ P) {
    int idx = blockIdx.x * 256 + threadIdx.x;  // 256*64
    int d = idx >> 6, k = idx & 63;
    float v = 0.f;
    if (k < 16) v = Wl[d * 16 + k];
    else if (k < 32) v = pks[(k - 16) * 256 + d];
    P[d * 64 + k] = v;
}

// ---------------- per-class constants ----------------
__global__ void consts_kernel(const float* __restrict__ Wl, const float* __restrict__ pks,
                              float* __restrict__ kc) {
    int k = threadIdx.x >> 5, lane = threadIdx.x & 31;
    float p2 = 0.f, pa = 0.f, a2 = 0.f;
    for (int d = lane; d < 256; d += 32) {
        float p = pks[k * 256 + d];
        float a = Wl[d * 16 + k];
        p2 += p * p; pa += p * a; a2 += a * a;
    }
    p2 = wsum(p2); pa = wsum(pa); a2 = wsum(a2);
    if (lane == 0) {
        float an = fmaxf(sqrtf(a2), 1e-15f);
        kc[k * 4 + 0] = an;
        kc[k * 4 + 1] = pa;
        kc[k * 4 + 2] = p2;
        kc[k * 4 + 3] = 2.0f / fmaxf(1.0f - p2, 1e-10f);
    }
}

// ---------------- logits (closed-form mobius_add projections) ----------------
__global__ void logits_kernel(const float* __restrict__ S, const float* __restrict__ h2v,
                              const float* __restrict__ kc, float* __restrict__ L) {
    int idx = blockIdx.x * 256 + threadIdx.x;  // 8192*16
    int i = idx >> 4, k = idx & 15;
    float ha = S[i * 64 + k];
    float ph = S[i * 64 + 16 + k];
    float h2 = h2v[i];
    float an = kc[k * 4 + 0], pa = kc[k * 4 + 1], p2 = kc[k * 4 + 2], lam = kc[k * 4 + 3];
    float alpha = 1.0f - 2.0f * ph + h2;
    float beta  = 1.0f - p2;
    float den = fmaxf(1.0f - 2.0f * ph + p2 * h2, 1e-15f);
    float za = (beta * ha - alpha * pa) / den;
    float zn2 = (beta * beta * h2 - 2.0f * alpha * beta * ph + alpha * alpha * p2) / (den * den);
    float dd = fmaxf(1.0f - zn2, 1e-10f) * an;
    L[idx] = lam * an * asinhf(2.0f * za / dd);
}

// ---------------- final GEMM: part[c] += A(rows, kchunk) @ logits ----------------
__global__ void __launch_bounds__(256) final_gemm_kernel(const float* __restrict__ A,
                                                         const float* __restrict__ L,
                                                         float* __restrict__ part) {
    __shared__ float As[16][518];
    __shared__ float Ls[16][18];
    int t = threadIdx.x;
    int mb = blockIdx.x * 512;
    int k0base = blockIdx.y * 512;
    unsigned long long acc[2][8];
#pragma unroll
    for (int r = 0; r < 2; r++)
#pragma unroll
        for (int j = 0; j < 8; j++) acc[r][j] = 0ull;

    for (int k0 = k0base; k0 < k0base + 512; k0 += 16) {
#pragma unroll
        for (int i = 0; i < 8; i++) {
            int idx = t + 256 * i;
            int r = idx >> 2;
            int q = (idx & 3) * 4;
            float4 v = *(const float4*)(A + (size_t)(mb + r) * NR + k0 + q);
            As[q + 0][r] = v.x; As[q + 1][r] = v.y;
            As[q + 2][r] = v.z; As[q + 3][r] = v.w;
        }
        if (t < 64) {
            int kk = t >> 2;
            int q = (t & 3) * 4;
            float4 v = *(const float4*)(L + (size_t)(k0 + kk) * 16 + q);
            Ls[kk][q] = v.x; Ls[kk][q + 1] = v.y; Ls[kk][q + 2] = v.z; Ls[kk][q + 3] = v.w;
        }
        __syncthreads();
#pragma unroll
        for (int kk = 0; kk < 16; kk++) {
            unsigned long long lv[8];
#pragma unroll
            for (int j = 0; j < 8; j++) lv[j] = *(const unsigned long long*)&Ls[kk][2 * j];
            float a0 = As[kk][t], a1 = As[kk][t + 256];
            unsigned long long ad0 = pack2(a0, a0);
            unsigned long long ad1 = pack2(a1, a1);
#pragma unroll
            for (int j = 0; j < 8; j++) {
                acc[0][j] = ffma2(ad0, lv[j], acc[0][j]);
                acc[1][j] = ffma2(ad1, lv[j], acc[1][j]);
            }
        }
        __syncthreads();
    }
    float* pb = part + (size_t)blockIdx.y * (NR * NC);
#pragma unroll
    for (int r2 = 0; r2 < 2; r2++) {
        int row = mb + t + r2 * 256;
#pragma unroll
        for (int j = 0; j < 4; j++) {
            float2 a = unpack2(acc[r2][2 * j]);
            float2 b = unpack2(acc[r2][2 * j + 1]);
            *(float4*)(pb + (size_t)row * NC + j * 4) = make_float4(a.x, a.y, b.x, b.y);
        }
    }
}

__global__ void reduce_final(const float* __restrict__ part, float* __restrict__ out) {
    int idx = blockIdx.x * 256 + threadIdx.x;  // 131072
    float s = 0.f;
#pragma unroll
    for (int c = 0; c < 16; c++) s += part[c * (NR * NC) + idx];
    out[idx] = s;
}

// ---------------- host ----------------
extern "C" void kernel_launch(void* const* d_in, const int* in_sizes, int n_in,
                              void* d_out, int out_size) {
    const float* X   = (const float*)d_in[0];
    const float* A   = (const float*)d_in[1];
    const float* W   = (const float*)d_in[2];
    const float* Wl  = (const float*)d_in[3];
    const float* pks = (const float*)d_in[4];
    float* out = (float*)d_out;

    void *buf1, *buf2, *gm1, *den, *srow, *h2, *P, *S, *kc, *Lg, *part;
    void *ahi, *alo, *bthi, *btlo;
    cudaGetSymbolAddress(&buf1, g_buf1);
    cudaGetSymbolAddress(&buf2, g_buf2);
    cudaGetSymbolAddress(&gm1, g_gm1);
    cudaGetSymbolAddress(&den, g_denom);
    cudaGetSymbolAddress(&srow, g_srow);
    cudaGetSymbolAddress(&h2, g_h2);
    cudaGetSymbolAddress(&P, g_p);
    cudaGetSymbolAddress(&S, g_s);
    cudaGetSymbolAddress(&kc, g_kc);
    cudaGetSymbolAddress(&Lg, g_logits);
    cudaGetSymbolAddress(&part, g_part);
    cudaGetSymbolAddress(&ahi, g_ahi);
    cudaGetSymbolAddress(&alo, g_alo);
    cudaGetSymbolAddress(&bthi, g_bthi);
    cudaGetSymbolAddress(&btlo, g_btlo);

    cudaFuncSetAttribute(hmma_gemm_kernel, cudaFuncAttributeMaxDynamicSharedMemorySize,
                         SMEM_TOTAL_MMA);

    // 1. mx = X @ W^T (direct NT GEMM; transpose pass eliminated)
    gemm_xwt<<<dim3(64, 4), 256>>>(X, W, (float*)buf1);
    // 2. fused: scale rows + gamma + transposed bf16 split of Bg
    rowwise_trans<<<256, 256>>>(X, (const float*)buf1,
                                (unsigned short*)bthi, (unsigned short*)btlo, (float*)gm1);
    // 3. A -> A_hi/A_lo (+ fused denom/srow row reductions)
    convertA_dot<<<NR, 256>>>(A, (const float*)gm1, (unsigned short*)ahi,
                              (unsigned short*)alo, (float*)den, (float*)srow);
    // 4. nom = A @ Bg via tensor cores (split-bf16, fp32 accumulate) -- profiled launch
    hmma_gemm_kernel<<<128, 256, SMEM_TOTAL_MMA>>>((const unsigned short*)ahi,
                                                   (const unsigned short*)alo,
                                                   (const unsigned short*)bthi,
                                                   (const unsigned short*)btlo,
                                                   (float*)buf2);
    // 5. H1, h2
    rowwise_h1_kernel<<<1024, 256>>>((const float*)buf2, (const float*)den,
                                     (const float*)srow, (float*)buf1, (float*)h2);
    // 6. P, per-class constants
    buildP_kernel<<<64, 256>>>(Wl, pks, (float*)P);
    consts_kernel<<<1, 512>>>(Wl, pks, (float*)kc);
    // 7. S = H1 @ P
    gemm_nn_kernel<<<dim3(64, 1), 256>>>((const float*)buf1, (const float*)P, (float*)S, DIM, 64);
    // 8. logits
    logits_kernel<<<512, 256>>>((const float*)S, (const float*)h2, (const float*)kc, (float*)Lg);
    // 9. out = A @ logits (split-K) + reduce
    final_gemm_kernel<<<dim3(16, 16), 256>>>(A, (const float*)Lg, (float*)part);
    reduce_final<<<512, 256>>>((const float*)part, out);
}

// round 13
// speedup vs baseline: 1.2013x; 1.2013x over previous
#include <cuda_runtime.h>
#include <cuda_bf16.h>
#include <cuda_fp16.h>
#include <math.h>

#define NR 8192
#define DIM 256
#define NC 16

// ---------------- scratch (device globals; no allocation) ----------------
__device__ float g_buf1[NR * DIM];     // mx -> H1
__device__ float g_buf2[NR * DIM];     // nom
__device__ float g_gm1[NR];
__device__ float g_denom[NR];
__device__ float g_srow[NR];
__device__ float g_h2[NR];
__device__ float g_p[DIM * 64];        // [W_logits | p_ks^T | 0-pad] (256 x 64)
__device__ float g_s[NR * 64];         // H1 @ P
__device__ float g_kc[NC * 4];         // a_n, pa, p2, lam
__device__ float g_logits[NR * NC];
__device__ float g_part[16 * NR * NC]; // split-K partials of final GEMM
// fp16 operands for the big tensor-core GEMM (A scaled by 2^14, split hi/lo; B single)
__device__ unsigned short g_ahi[NR * NR];        // 128 MB
__device__ unsigned short g_alo[NR * NR];        // 128 MB
__device__ unsigned short g_bthi[DIM * NR];      // Bg^T fp16 (256 x 8192)

#define A_SCALE 16384.0f
#define A_UNSCALE 6.103515625e-05f   // 2^-14

// ---------------- helpers ----------------
__device__ __forceinline__ unsigned long long pack2(float lo, float hi) {
    unsigned long long r;
    asm("mov.b64 %0, {%1, %2};" : "=l"(r) : "r"(__float_as_uint(lo)), "r"(__float_as_uint(hi)));
    return r;
}
__device__ __forceinline__ float2 unpack2(unsigned long long v) {
    unsigned int lo, hi;
    asm("mov.b64 {%0, %1}, %2;" : "=r"(lo), "=r"(hi) : "l"(v));
    float2 f; f.x = __uint_as_float(lo); f.y = __uint_as_float(hi); return f;
}
__device__ __forceinline__ unsigned long long ffma2(unsigned long long a, unsigned long long b,
                                                    unsigned long long c) {
    unsigned long long d;
    asm("fma.rn.f32x2 %0, %1, %2, %3;" : "=l"(d) : "l"(a), "l"(b), "l"(c));
    return d;
}
__device__ __forceinline__ float wsum(float v) {
#pragma unroll
    for (int o = 16; o; o >>= 1) v += __shfl_xor_sync(0xffffffffu, v, o);
    return v;
}
__device__ __forceinline__ float atanh_clip(float x) {
    return atanhf(fminf(x, 1.0f - 1e-7f));
}
__device__ __forceinline__ unsigned int smem_u32(const void* p) {
    unsigned int a;
    asm("{ .reg .u64 t; cvta.to.shared.u64 t, %1; cvt.u32.u64 %0, t; }" : "=r"(a) : "l"(p));
    return a;
}
__device__ __forceinline__ void ldsm4(unsigned* r, unsigned addr) {
    asm volatile("ldmatrix.sync.aligned.m8n8.x4.shared.b16 {%0,%1,%2,%3}, [%4];"
                 : "=r"(r[0]), "=r"(r[1]), "=r"(r[2]), "=r"(r[3]) : "r"(addr));
}
__device__ __forceinline__ void mma_f16(float* d, const unsigned* a,
                                        unsigned b0, unsigned b1) {
    asm volatile(
        "mma.sync.aligned.m16n8k16.row.col.f32.f16.f16.f32 "
        "{%0,%1,%2,%3}, {%4,%5,%6,%7}, {%8,%9}, {%0,%1,%2,%3};"
        : "+f"(d[0]), "+f"(d[1]), "+f"(d[2]), "+f"(d[3])
        : "r"(a[0]), "r"(a[1]), "r"(a[2]), "r"(a[3]), "r"(b0), "r"(b1));
}

// ---------------- mx = X @ W^T (NT GEMM) ----------------
__global__ void __launch_bounds__(256) gemm_xwt(const float* __restrict__ X,
                                                const float* __restrict__ W,
                                                float* __restrict__ C) {
    __shared__ float As[16][132];
    __shared__ float Bs[16][64];
    int t = threadIdx.x;
    int bm = blockIdx.x * 128;
    int bn = blockIdx.y * 64;
    int m0 = (t >> 4) * 8;
    int n0 = (t & 15) * 4;
    int arow = t >> 2;
    int aq = (t & 3) * 4;
    unsigned long long acc[8][2];
#pragma unroll
    for (int i = 0; i < 8; i++) { acc[i][0] = 0ull; acc[i][1] = 0ull; }

    for (int k0 = 0; k0 < DIM; k0 += 16) {
#pragma unroll
        for (int i = 0; i < 2; i++) {
            int r = arow + i * 64;
            float4 v = *(const float4*)(X + (size_t)(bm + r) * DIM + k0 + aq);
            As[aq + 0][r] = v.x; As[aq + 1][r] = v.y;
            As[aq + 2][r] = v.z; As[aq + 3][r] = v.w;
        }
        {
            int r = t >> 2;
            float4 v = *(const float4*)(W + (size_t)(bn + r) * DIM + k0 + aq);
            Bs[aq + 0][r] = v.x; Bs[aq + 1][r] = v.y;
            Bs[aq + 2][r] = v.z; Bs[aq + 3][r] = v.w;
        }
        __syncthreads();
#pragma unroll
        for (int kk = 0; kk < 16; kk++) {
            float4 a0 = *(const float4*)&As[kk][m0];
            float4 a1 = *(const float4*)&As[kk][m0 + 4];
            float4 b  = *(const float4*)&Bs[kk][n0];
            unsigned long long b01 = pack2(b.x, b.y);
            unsigned long long b23 = pack2(b.z, b.w);
            float am[8] = {a0.x, a0.y, a0.z, a0.w, a1.x, a1.y, a1.z, a1.w};
#pragma unroll
            for (int i = 0; i < 8; i++) {
                unsigned long long ad = pack2(am[i], am[i]);
                acc[i][0] = ffma2(ad, b01, acc[i][0]);
                acc[i][1] = ffma2(ad, b23, acc[i][1]);
            }
        }
        __syncthreads();
    }
#pragma unroll
    for (int i = 0; i < 8; i++) {
        float2 lo = unpack2(acc[i][0]);
        float2 hi = unpack2(acc[i][1]);
        *(float4*)(C + (size_t)(bm + m0 + i) * DIM + bn + n0) =
            make_float4(lo.x, lo.y, hi.x, hi.y);
    }
}

// ---------------- generic NN GEMM (kept for S = H1 @ P) ----------------
__global__ void __launch_bounds__(256) gemm_nn_kernel(const float* __restrict__ A,
                                                      const float* __restrict__ B,
                                                      float* __restrict__ C,
                                                      int K, int N) {
    __shared__ float As[16][132];
    __shared__ float Bs[16][64];
    int t = threadIdx.x;
    int bm = blockIdx.x * 128;
    int bn = blockIdx.y * 64;
    int m0 = (t >> 4) * 8;
    int n0 = (t & 15) * 4;
    int arow = t >> 2;
    int aq = (t & 3) * 4;
    int brow = t >> 4;
    int bq = (t & 15) * 4;
    unsigned long long acc[8][2];
#pragma unroll
    for (int i = 0; i < 8; i++) { acc[i][0] = 0ull; acc[i][1] = 0ull; }
    const float* Ab = A + (size_t)bm * K;
    const float* Bb = B + bn;
    for (int k0 = 0; k0 < K; k0 += 16) {
#pragma unroll
        for (int i = 0; i < 2; i++) {
            int r = arow + i * 64;
            float4 v = *(const float4*)(Ab + (size_t)r * K + k0 + aq);
            As[aq + 0][r] = v.x; As[aq + 1][r] = v.y;
            As[aq + 2][r] = v.z; As[aq + 3][r] = v.w;
        }
        {
            float4 v = *(const float4*)(Bb + (size_t)(k0 + brow) * N + bq);
            *(float4*)&Bs[brow][bq] = v;
        }
        __syncthreads();
#pragma unroll
        for (int kk = 0; kk < 16; kk++) {
            float4 a0 = *(const float4*)&As[kk][m0];
            float4 a1 = *(const float4*)&As[kk][m0 + 4];
            float4 b  = *(const float4*)&Bs[kk][n0];
            unsigned long long b01 = pack2(b.x, b.y);
            unsigned long long b23 = pack2(b.z, b.w);
            float am[8] = {a0.x, a0.y, a0.z, a0.w, a1.x, a1.y, a1.z, a1.w};
#pragma unroll
            for (int i = 0; i < 8; i++) {
                unsigned long long ad = pack2(am[i], am[i]);
                acc[i][0] = ffma2(ad, b01, acc[i][0]);
                acc[i][1] = ffma2(ad, b23, acc[i][1]);
            }
        }
        __syncthreads();
    }
#pragma unroll
    for (int i = 0; i < 8; i++) {
        float2 lo = unpack2(acc[i][0]);
        float2 hi = unpack2(acc[i][1]);
        float4 v = make_float4(lo.x, lo.y, hi.x, hi.y);
        *(float4*)(C + (size_t)(bm + m0 + i) * N + bn + n0) = v;
    }
}

// ---------------- fused: mobius scale + gamma + transposed fp16 B ----------------
__global__ void __launch_bounds__(256) rowwise_trans(const float* __restrict__ X,
                                                     const float* __restrict__ MX,
                                                     unsigned short* __restrict__ Thi,
                                                     float* __restrict__ gm1) {
    __shared__ float sm[32][257];
    int jb = blockIdx.x * 32;
    int wd = threadIdx.x >> 5, lane = threadIdx.x & 31;
#pragma unroll
    for (int rr = 0; rr < 4; rr++) {
        int lr = wd * 4 + rr;
        int j = jb + lr;
        const float4* xr = (const float4*)(X + (size_t)j * DIM) + lane * 2;
        const float4* mr = (const float4*)(MX + (size_t)j * DIM) + lane * 2;
        float4 x0 = xr[0], x1 = xr[1];
        float4 m0 = mr[0], m1 = mr[1];
        float xs = x0.x * x0.x + x0.y * x0.y + x0.z * x0.z + x0.w * x0.w +
                   x1.x * x1.x + x1.y * x1.y + x1.z * x1.z + x1.w * x1.w;
        float ms = m0.x * m0.x + m0.y * m0.y + m0.z * m0.z + m0.w * m0.w +
                   m1.x * m1.x + m1.y * m1.y + m1.z * m1.z + m1.w * m1.w;
        xs = wsum(xs); ms = wsum(ms);
        float xn  = fmaxf(sqrtf(xs), 1e-15f);
        float mxn = fmaxf(sqrtf(ms), 1e-15f);
        float s = tanhf(mxn / xn * atanh_clip(xn)) / mxn;
        float g = 2.0f / fmaxf(1.0f - s * s * ms, 1e-10f);
        float gs = g * s;
        int d0 = lane * 8;
        sm[lr][d0 + 0] = m0.x * gs; sm[lr][d0 + 1] = m0.y * gs;
        sm[lr][d0 + 2] = m0.z * gs; sm[lr][d0 + 3] = m0.w * gs;
        sm[lr][d0 + 4] = m1.x * gs; sm[lr][d0 + 5] = m1.y * gs;
        sm[lr][d0 + 6] = m1.z * gs; sm[lr][d0 + 7] = m1.w * gs;
        if (lane == 0) gm1[j] = g - 1.0f;
    }
    __syncthreads();
    int gidx = threadIdx.x >> 3;
    int l3 = threadIdx.x & 7;
#pragma unroll
    for (int pass = 0; pass < 8; pass++) {
        int d = pass * 32 + gidx;
        unsigned short h4[4];
#pragma unroll
        for (int jj = 0; jj < 4; jj++) {
            float v = sm[l3 * 4 + jj][d];
            h4[jj] = __half_as_ushort(__float2half_rn(v));
        }
        uint2 hv;
        hv.x = (unsigned)h4[0] | ((unsigned)h4[1] << 16);
        hv.y = (unsigned)h4[2] | ((unsigned)h4[3] << 16);
        *(uint2*)(Thi + (size_t)d * NR + jb + l3 * 4) = hv;
    }
}

// ---------------- convert A -> fp16 hi/lo of A*2^14, fused row dots ----------------
__global__ void __launch_bounds__(256) convertA_dot(const float* __restrict__ A,
                                                    const float* __restrict__ gm1,
                                                    unsigned short* __restrict__ Ahi,
                                                    unsigned short* __restrict__ Alo,
                                                    float* __restrict__ denom,
                                                    float* __restrict__ srow) {
    int row = blockIdx.x;
    const float4* ar = (const float4*)(A + (size_t)row * NR);
    const float4* gr = (const float4*)gm1;
    uint2* hi4 = (uint2*)(Ahi + (size_t)row * NR);
    uint2* lo4 = (uint2*)(Alo + (size_t)row * NR);
    float d = 0.f, ss = 0.f;
    for (int j = threadIdx.x; j < NR / 4; j += 256) {
        float4 a = ar[j];
        float4 g = gr[j];
        d += a.x * g.x + a.y * g.y + a.z * g.z + a.w * g.w;
        ss += a.x + a.y + a.z + a.w;
        float av[4] = {a.x, a.y, a.z, a.w};
        unsigned int hb[4], lb[4];
#pragma unroll
        for (int q = 0; q < 4; q++) {
            float as = av[q] * A_SCALE;
            __half h = __float2half_rn(as);
            float rem = as - __half2float(h);
            __half l = __float2half_rn(rem);
            hb[q] = __half_as_ushort(h);
            lb[q] = __half_as_ushort(l);
        }
        uint2 hv, lv;
        hv.x = hb[0] | (hb[1] << 16); hv.y = hb[2] | (hb[3] << 16);
        lv.x = lb[0] | (lb[1] << 16); lv.y = lb[2] | (lb[3] << 16);
        hi4[j] = hv; lo4[j] = lv;
    }
    __shared__ float sd[8], sss[8];
    d = wsum(d); ss = wsum(ss);
    int lane = threadIdx.x & 31, wp = threadIdx.x >> 5;
    if (lane == 0) { sd[wp] = d; sss[wp] = ss; }
    __syncthreads();
    if (wp == 0) {
        d = (lane < 8) ? sd[lane] : 0.f;
        ss = (lane < 8) ? sss[lane] : 0.f;
        d = wsum(d); ss = wsum(ss);
        if (lane == 0) {
            if (fabsf(d) < 1e-10f) d = 1e-10f;
            denom[row] = d;
            srow[row] = ss;
        }
    }
}

// ---------------- big GEMM via mma.sync (fp16 2-product, fp32 accum) ----------------
// Stage = Ahi(16KB) | Alo(16KB) | B(16KB) = 48KB. 4 stages = 192KB.
#define STG_BYTES 49152
#define SMEM_TOTAL_MMA (4 * STG_BYTES)

__device__ __forceinline__ void load_stage(unsigned int sb, int s, int k0, int bm, int bn,
                                           const unsigned short* Ahi, const unsigned short* Alo,
                                           const unsigned short* Bh, int tid) {
    unsigned int stg = sb + s * STG_BYTES;
#pragma unroll
    for (int t = 0; t < 12; t++) {
        int idx = tid + 256 * t;              // 0..3071
        int tile = idx >> 10;                 // 0..2
        int c = idx & 1023;
        int r = c >> 3;                       // 0..127
        int ch = c & 7;                       // 16B chunk in 128B row
        const unsigned short* g;
        int grow;
        if (tile == 0)      { g = Ahi; grow = bm + r; }
        else if (tile == 1) { g = Alo; grow = bm + r; }
        else                { g = Bh;  grow = bn + r; }
        const unsigned short* src = g + (size_t)grow * NR + k0 + ch * 8;
        unsigned int off = (unsigned)(r << 7) + (unsigned)(ch << 4);
        unsigned int dst = stg + (tile << 14) + (off ^ ((off >> 3) & 0x70));
        asm volatile("cp.async.cg.shared.global [%0], [%1], 16;" :: "r"(dst), "l"(src));
    }
}

__global__ void __launch_bounds__(256, 1) hmma_gemm_kernel(const unsigned short* __restrict__ Ahi,
                                                           const unsigned short* __restrict__ Alo,
                                                           const unsigned short* __restrict__ Bh,
                                                           float* __restrict__ C) {
    extern __shared__ char smem[];
    unsigned int sb = smem_u32(smem);
    int tid = threadIdx.x;
    int wid = tid >> 5;
    int lane = tid & 31;
    int bm = (blockIdx.x >> 1) * 128;
    int bn = (blockIdx.x & 1) * 128;
    int wm = (wid & 3) * 32;
    int wn = (wid >> 2) * 64;

    int lrow = (lane & 7) + ((lane >> 3) & 1) * 8;
    int lcol = (lane >> 4) * 16;

    float acc[2][8][4];
#pragma unroll
    for (int a = 0; a < 2; a++)
#pragma unroll
        for (int b = 0; b < 8; b++)
#pragma unroll
            for (int c = 0; c < 4; c++) acc[a][b][c] = 0.f;

#pragma unroll
    for (int s = 0; s < 4; s++) {
        load_stage(sb, s, s * 64, bm, bn, Ahi, Alo, Bh, tid);
        asm volatile("cp.async.commit_group;" ::: "memory");
    }

    for (int k = 0; k < 128; k++) {
        int s = k & 3;
        asm volatile("cp.async.wait_group 3;" ::: "memory");
        __syncthreads();
        unsigned int stg = sb + s * STG_BYTES;
#pragma unroll
        for (int ks = 0; ks < 4; ks++) {
            int bcol = ks * 32 + lcol;
            unsigned Ah[2][4], Al[2][4];
#pragma unroll
            for (int mf = 0; mf < 2; mf++) {
                int row = wm + mf * 16 + lrow;
                unsigned base = (unsigned)(row << 7) + ((unsigned)bcol ^ ((row & 7) << 4));
                ldsm4(Ah[mf], stg + base);
                ldsm4(Al[mf], stg + 16384 + base);
            }
            unsigned Bf[4][4];
#pragma unroll
            for (int g = 0; g < 4; g++) {
                int row = wn + g * 16 + lrow;
                unsigned base = (unsigned)(row << 7) + ((unsigned)bcol ^ ((row & 7) << 4));
                ldsm4(Bf[g], stg + 32768 + base);
            }
#pragma unroll
            for (int mf = 0; mf < 2; mf++)
#pragma unroll
                for (int g = 0; g < 4; g++)
#pragma unroll
                    for (int j = 0; j < 2; j++) {
                        float* d = acc[mf][g * 2 + j];
                        mma_f16(d, Ah[mf], Bf[g][j], Bf[g][j + 2]);
                        mma_f16(d, Al[mf], Bf[g][j], Bf[g][j + 2]);
                    }
        }
        __syncthreads();
        if (k + 4 < 128)
            load_stage(sb, s, (k + 4) * 64, bm, bn, Ahi, Alo, Bh, tid);
        asm volatile("cp.async.commit_group;" ::: "memory");
    }

    // epilogue: un-scale (A was x2^14) and write
#pragma unroll
    for (int mf = 0; mf < 2; mf++) {
        int row0 = bm + wm + mf * 16 + (lane >> 2);
#pragma unroll
        for (int f = 0; f < 8; f++) {
            int col = bn + wn + f * 8 + (lane & 3) * 2;
            *(float2*)&C[(size_t)row0 * DIM + col] =
                make_float2(acc[mf][f][0] * A_UNSCALE, acc[mf][f][1] * A_UNSCALE);
            *(float2*)&C[(size_t)(row0 + 8) * DIM + col] =
                make_float2(acc[mf][f][2] * A_UNSCALE, acc[mf][f][3] * A_UNSCALE);
        }
    }
}

// ---------------- row-wise 2: two_mean -> H1, h2 ----------------
__global__ void __launch_bounds__(256) rowwise_h1_kernel(const float* __restrict__ NOM,
                                                         const float* __restrict__ denom,
                                                         const float* __restrict__ srow,
                                                         float* __restrict__ H1,
                                                         float* __restrict__ h2out) {
    int w = (blockIdx.x << 3) + (threadIdx.x >> 5);
    int lane = threadIdx.x & 31;
    const float4* nr = (const float4*)(NOM + (size_t)w * DIM) + lane * 2;
    float4 v0 = nr[0], v1 = nr[1];
    float dinv = 1.0f / denom[w];
    float t[8] = {v0.x * dinv, v0.y * dinv, v0.z * dinv, v0.w * dinv,
                  v1.x * dinv, v1.y * dinv, v1.z * dinv, v1.w * dinv};
    float s2 = 0.f;
#pragma unroll
    for (int i = 0; i < 8; i++) s2 += t[i] * t[i];
    s2 = wsum(s2);
    float tn = fmaxf(sqrtf(s2), 1e-15f);
    float c1 = tanhf(0.5f * atanh_clip(tn)) / tn;
#pragma unroll
    for (int i = 0; i < 8; i++) t[i] *= c1;
    s2 = 0.f;
#pragma unroll
    for (int i = 0; i < 8; i++) s2 += t[i] * t[i];
    s2 = wsum(s2);
    float mn = fmaxf(sqrtf(s2), 1e-15f);
    float c2 = tanhf(srow[w] * atanh_clip(mn)) / mn;
#pragma unroll
    for (int i = 0; i < 8; i++) t[i] *= c2;
    s2 = 0.f;
#pragma unroll
    for (int i = 0; i < 8; i++) s2 += t[i] * t[i];
    s2 = wsum(s2);
    float yn = fmaxf(sqrtf(s2), 1e-15f);
    float c3 = atanh_clip(yn) / yn;
#pragma unroll
    for (int i = 0; i < 8; i++) t[i] = fmaxf(t[i] * c3, 0.0f);
    s2 = 0.f;
#pragma unroll
    for (int i = 0; i < 8; i++) s2 += t[i] * t[i];
    s2 = wsum(s2);
    float rn = fmaxf(sqrtf(s2), 1e-15f);
    float c4 = tanhf(rn) / rn;
#pragma unroll
    for (int i = 0; i < 8; i++) t[i] *= c4;
    s2 = 0.f;
#pragma unroll
    for (int i = 0; i < 8; i++) s2 += t[i] * t[i];
    s2 = wsum(s2);
    float4* hr = (float4*)(H1 + (size_t)w * DIM) + lane * 2;
    hr[0] = make_float4(t[0], t[1], t[2], t[3]);
    hr[1] = make_float4(t[4], t[5], t[6], t[7]);
    if (lane == 0) h2out[w] = s2;
}

// ---------------- build P = [W_logits | p_ks^T | 0] (256 x 64) ----------------
__global__ void buildP_kernel(const float* __restrict__ Wl, const float* __restrict__ pks,
                              float* __restrict__ P) {
    int idx = blockIdx.x * 256 + threadIdx.x;
    int d = idx >> 6, k = idx & 63;
    float v = 0.f;
    if (k < 16) v = Wl[d * 16 + k];
    else if (k < 32) v = pks[(k - 16) * 256 + d];
    P[d * 64 + k] = v;
}

// ---------------- per-class constants ----------------
__global__ void consts_kernel(const float* __restrict__ Wl, const float* __restrict__ pks,
                              float* __restrict__ kc) {
    int k = threadIdx.x >> 5, lane = threadIdx.x & 31;
    float p2 = 0.f, pa = 0.f, a2 = 0.f;
    for (int d = lane; d < 256; d += 32) {
        float p = pks[k * 256 + d];
        float a = Wl[d * 16 + k];
        p2 += p * p; pa += p * a; a2 += a * a;
    }
    p2 = wsum(p2); pa = wsum(pa); a2 = wsum(a2);
    if (lane == 0) {
        float an = fmaxf(sqrtf(a2), 1e-15f);
        kc[k * 4 + 0] = an;
        kc[k * 4 + 1] = pa;
        kc[k * 4 + 2] = p2;
        kc[k * 4 + 3] = 2.0f / fmaxf(1.0f - p2, 1e-10f);
    }
}

// ---------------- logits (closed-form mobius_add projections) ----------------
__global__ void logits_kernel(const float* __restrict__ S, const float* __restrict__ h2v,
                              const float* __restrict__ kc, float* __restrict__ L) {
    int idx = blockIdx.x * 256 + threadIdx.x;
    int i = idx >> 4, k = idx & 15;
    float ha = S[i * 64 + k];
    float ph = S[i * 64 + 16 + k];
    float h2 = h2v[i];
    float an = kc[k * 4 + 0], pa = kc[k * 4 + 1], p2 = kc[k * 4 + 2], lam = kc[k * 4 + 3];
    float alpha = 1.0f - 2.0f * ph + h2;
    float beta  = 1.0f - p2;
    float den = fmaxf(1.0f - 2.0f * ph + p2 * h2, 1e-15f);
    float za = (beta * ha - alpha * pa) / den;
    float zn2 = (beta * beta * h2 - 2.0f * alpha * beta * ph + alpha * alpha * p2) / (den * den);
    float dd = fmaxf(1.0f - zn2, 1e-10f) * an;
    L[idx] = lam * an * asinhf(2.0f * za / dd);
}

// ---------------- final GEMM: part[c] += A(rows, kchunk) @ logits ----------------
__global__ void __launch_bounds__(256) final_gemm_kernel(const float* __restrict__ A,
                                                         const float* __restrict__ L,
                                                         float* __restrict__ part) {
    __shared__ float As[16][518];
    __shared__ float Ls[16][18];
    int t = threadIdx.x;
    int mb = blockIdx.x * 512;
    int k0base = blockIdx.y * 512;
    unsigned long long acc[2][8];
#pragma unroll
    for (int r = 0; r < 2; r++)
#pragma unroll
        for (int j = 0; j < 8; j++) acc[r][j] = 0ull;

    for (int k0 = k0base; k0 < k0base + 512; k0 += 16) {
#pragma unroll
        for (int i = 0; i < 8; i++) {
            int idx = t + 256 * i;
            int r = idx >> 2;
            int q = (idx & 3) * 4;
            float4 v = *(const float4*)(A + (size_t)(mb + r) * NR + k0 + q);
            As[q + 0][r] = v.x; As[q + 1][r] = v.y;
            As[q + 2][r] = v.z; As[q + 3][r] = v.w;
        }
        if (t < 64) {
            int kk = t >> 2;
            int q = (t & 3) * 4;
            float4 v = *(const float4*)(L + (size_t)(k0 + kk) * 16 + q);
            Ls[kk][q] = v.x; Ls[kk][q + 1] = v.y; Ls[kk][q + 2] = v.z; Ls[kk][q + 3] = v.w;
        }
        __syncthreads();
#pragma unroll
        for (int kk = 0; kk < 16; kk++) {
            unsigned long long lv[8];
#pragma unroll
            for (int j = 0; j < 8; j++) lv[j] = *(const unsigned long long*)&Ls[kk][2 * j];
            float a0 = As[kk][t], a1 = As[kk][t + 256];
            unsigned long long ad0 = pack2(a0, a0);
            unsigned long long ad1 = pack2(a1, a1);
#pragma unroll
            for (int j = 0; j < 8; j++) {
                acc[0][j] = ffma2(ad0, lv[j], acc[0][j]);
                acc[1][j] = ffma2(ad1, lv[j], acc[1][j]);
            }
        }
        __syncthreads();
    }
    float* pb = part + (size_t)blockIdx.y * (NR * NC);
#pragma unroll
    for (int r2 = 0; r2 < 2; r2++) {
        int row = mb + t + r2 * 256;
#pragma unroll
        for (int j = 0; j < 4; j++) {
            float2 a = unpack2(acc[r2][2 * j]);
            float2 b = unpack2(acc[r2][2 * j + 1]);
            *(float4*)(pb + (size_t)row * NC + j * 4) = make_float4(a.x, a.y, b.x, b.y);
        }
    }
}

__global__ void reduce_final(const float* __restrict__ part, float* __restrict__ out) {
    int idx = blockIdx.x * 256 + threadIdx.x;
    float s = 0.f;
#pragma unroll
    for (int c = 0; c < 16; c++) s += part[c * (NR * NC) + idx];
    out[idx] = s;
}

// ---------------- host ----------------
extern "C" void kernel_launch(void* const* d_in, const int* in_sizes, int n_in,
                              void* d_out, int out_size) {
    const float* X   = (const float*)d_in[0];
    const float* A   = (const float*)d_in[1];
    const float* W   = (const float*)d_in[2];
    const float* Wl  = (const float*)d_in[3];
    const float* pks = (const float*)d_in[4];
    float* out = (float*)d_out;

    void *buf1, *buf2, *gm1, *den, *srow, *h2, *P, *S, *kc, *Lg, *part;
    void *ahi, *alo, *bthi;
    cudaGetSymbolAddress(&buf1, g_buf1);
    cudaGetSymbolAddress(&buf2, g_buf2);
    cudaGetSymbolAddress(&gm1, g_gm1);
    cudaGetSymbolAddress(&den, g_denom);
    cudaGetSymbolAddress(&srow, g_srow);
    cudaGetSymbolAddress(&h2, g_h2);
    cudaGetSymbolAddress(&P, g_p);
    cudaGetSymbolAddress(&S, g_s);
    cudaGetSymbolAddress(&kc, g_kc);
    cudaGetSymbolAddress(&Lg, g_logits);
    cudaGetSymbolAddress(&part, g_part);
    cudaGetSymbolAddress(&ahi, g_ahi);
    cudaGetSymbolAddress(&alo, g_alo);
    cudaGetSymbolAddress(&bthi, g_bthi);

    cudaFuncSetAttribute(hmma_gemm_kernel, cudaFuncAttributeMaxDynamicSharedMemorySize,
                         SMEM_TOTAL_MMA);

    // 1. mx = X @ W^T
    gemm_xwt<<<dim3(64, 4), 256>>>(X, W, (float*)buf1);
    // 2. fused: scale rows + gamma + transposed fp16 B
    rowwise_trans<<<256, 256>>>(X, (const float*)buf1,
                                (unsigned short*)bthi, (float*)gm1);
    // 3. A -> fp16 hi/lo of A*2^14 (+ fused denom/srow)
    convertA_dot<<<NR, 256>>>(A, (const float*)gm1, (unsigned short*)ahi,
                              (unsigned short*)alo, (float*)den, (float*)srow);
    // 4. nom = A @ Bg via fp16 2-product tensor cores (profiled launch)
    hmma_gemm_kernel<<<128, 256, SMEM_TOTAL_MMA>>>((const unsigned short*)ahi,
                                                   (const unsigned short*)alo,
                                                   (const unsigned short*)bthi,
                                                   (float*)buf2);
    // 5. H1, h2
    rowwise_h1_kernel<<<1024, 256>>>((const float*)buf2, (const float*)den,
                                     (const float*)srow, (float*)buf1, (float*)h2);
    // 6. P, per-class constants
    buildP_kernel<<<64, 256>>>(Wl, pks, (float*)P);
    consts_kernel<<<1, 512>>>(Wl, pks, (float*)kc);
    // 7. S = H1 @ P
    gemm_nn_kernel<<<dim3(64, 1), 256>>>((const float*)buf1, (const float*)P, (float*)S, DIM, 64);
    // 8. logits
    logits_kernel<<<512, 256>>>((const float*)S, (const float*)h2, (const float*)kc, (float*)Lg);
    // 9. out = A @ logits (split-K) + reduce
    final_gemm_kernel<<<dim3(16, 16), 256>>>(A, (const float*)Lg, (float*)part);
    reduce_final<<<512, 256>>>((const float*)part, out);
}